// round 1
// baseline (speedup 1.0000x reference)
#include <cuda_runtime.h>

// ---------------- problem constants ----------------
#define CDIM 128
#define MAXN 25600          // N = 25000
#define MAXE 404000         // E = 400000
#define TILE 128            // rows (edges/nodes) per block tile
#define NTHREADS 256
#define SP_STRIDE 66        // P2 row stride in ull (float2) units, padded

// ---------------- device scratch (no allocs allowed) ----------------
__device__ float g_K[(size_t)MAXN * CDIM];   // exp(min(k,60)) per node
__device__ float g_V[(size_t)MAXN * CDIM];   // w[c] * v per node
__device__ float g_R[(size_t)MAXN * CDIM];   // sigmoid(r) per node
__device__ float g_w[CDIM];
__device__ int   g_s[MAXE];
__device__ int   g_t[MAXE];
__device__ int   g_is64;

// ---------------- helpers ----------------
union U64F2 { unsigned long long u; float2 f; };

__device__ __forceinline__ void ffma2(unsigned long long& d,
                                      unsigned long long a,
                                      unsigned long long b) {
    asm("fma.rn.f32x2 %0, %1, %2, %3;" : "=l"(d) : "l"(a), "l"(b), "l"(d));
}

// ---------------- prep: per-channel decay w, index dtype detection ----------------
__global__ void prep_kernel(const float* __restrict__ time_w,
                            const void* ip, const void* Tp,
                            const void* sraw) {
    int c = threadIdx.x;
    if (c < CDIM) {
        // low 32-bit word is the value for both LE int32 and small LE int64
        int iv = *(const int*)ip;
        int Tv = *(const int*)Tp;
        float f = -(float)(Tv - iv - 1);
        g_w[c] = __expf(f * time_w[c]);
    }
    if (threadIdx.x == 0) {
        // If s is int64, every odd 32-bit word is 0 (values in [0, N), N small).
        const int* w = (const int*)sraw;
        int any = 0;
#pragma unroll
        for (int k = 0; k < 64; ++k) any |= w[2 * k + 1];
        g_is64 = (any == 0) ? 1 : 0;
    }
}

__global__ void idx_kernel(const void* sraw, const void* traw, int E) {
    int e = blockIdx.x * blockDim.x + threadIdx.x;
    if (e >= E) return;
    if (g_is64) {
        g_s[e] = (int)((const long long*)sraw)[e];
        g_t[e] = (int)((const long long*)traw)[e];
    } else {
        g_s[e] = ((const int*)sraw)[e];
        g_t[e] = ((const int*)traw)[e];
    }
}

// ---------------- shared GEMM core ----------------
// smem layout (dynamic): WP[64*128] ull (W as c-pairs: WP[cp*128 + j] = (W[j][2cp], W[j][2cp+1]))
//                        P2[128*SP_STRIDE] ull (input tile rows as c-pairs)
// Thread (ty = tid>>4, tx = tid&15) computes rows ty*8..ty*8+7, cols j = tx + 16*jj (jj=0..7).
// Accumulator lanes hold (sum over even c, sum over odd c); final = lane0 + lane1.

__device__ __forceinline__ void gemm_8x8(const unsigned long long* __restrict__ P2,
                                         const unsigned long long* __restrict__ WP,
                                         int ty, int tx,
                                         float out_sum[8][8]) {
    unsigned long long acc[8][8];
#pragma unroll
    for (int i = 0; i < 8; ++i)
#pragma unroll
        for (int j = 0; j < 8; ++j) acc[i][j] = 0ull;

    const unsigned long long* Pr = P2 + (size_t)(ty * 8) * SP_STRIDE;

#pragma unroll 4
    for (int cp = 0; cp < CDIM / 2; ++cp) {
        unsigned long long pv[8], wv[8];
#pragma unroll
        for (int i = 0; i < 8; ++i) pv[i] = Pr[i * SP_STRIDE + cp];
#pragma unroll
        for (int jj = 0; jj < 8; ++jj) wv[jj] = WP[cp * CDIM + tx + 16 * jj];
#pragma unroll
        for (int i = 0; i < 8; ++i)
#pragma unroll
            for (int jj = 0; jj < 8; ++jj) ffma2(acc[i][jj], pv[i], wv[jj]);
    }

#pragma unroll
    for (int i = 0; i < 8; ++i)
#pragma unroll
        for (int jj = 0; jj < 8; ++jj) {
            U64F2 u; u.u = acc[i][jj];
            out_sum[i][jj] = u.f.x + u.f.y;
        }
}

__device__ __forceinline__ void fill_WP(unsigned long long* WP,
                                        const float* __restrict__ W) {
    for (int idx = threadIdx.x; idx < (CDIM / 2) * CDIM; idx += NTHREADS) {
        int cp = idx >> 7;
        int j  = idx & (CDIM - 1);
        WP[idx] = *(const unsigned long long*)(W + j * CDIM + 2 * cp);
    }
}

// ---------------- node kernel: K/V/R = mix(x,prev) @ W.T with epilogues ----------------
extern __shared__ unsigned long long sm_dyn[];

__global__ __launch_bounds__(NTHREADS, 1)
void node_kernel(const float* __restrict__ x, const float* __restrict__ prevx,
                 const float* __restrict__ Wk, const float* __restrict__ Wv,
                 const float* __restrict__ Wr,
                 const float* __restrict__ tmk, const float* __restrict__ tmv,
                 const float* __restrict__ tmr, int N) {
    unsigned long long* WP = sm_dyn;
    unsigned long long* P2 = sm_dyn + (CDIM / 2) * CDIM;
    float* P2f = (float*)P2;

    int mat = blockIdx.y;
    const float* W  = (mat == 0) ? Wk  : (mat == 1) ? Wv  : Wr;
    const float* tm = (mat == 0) ? tmk : (mat == 1) ? tmv : tmr;

    fill_WP(WP, W);

    int tid  = threadIdx.x;
    int r0   = tid >> 1, half = tid & 1;
    int base = blockIdx.x * TILE;
    int node = base + r0;

    // phase 1: time-mix into P2 (c-paired layout)
    {
        float* dst = P2f + (size_t)r0 * (SP_STRIDE * 2) + half * 64;
        if (node < N) {
            const float4* x4 = (const float4*)(x    + (size_t)node * CDIM + half * 64);
            const float4* p4 = (const float4*)(prevx+ (size_t)node * CDIM + half * 64);
            const float4* t4 = (const float4*)(tm + half * 64);
#pragma unroll
            for (int q = 0; q < 16; ++q) {
                float4 xv = x4[q], pv = p4[q], tv = t4[q];
                float4 m;
                m.x = pv.x + tv.x * (xv.x - pv.x);
                m.y = pv.y + tv.y * (xv.y - pv.y);
                m.z = pv.z + tv.z * (xv.z - pv.z);
                m.w = pv.w + tv.w * (xv.w - pv.w);
                *(float4*)(dst + 4 * q) = m;
            }
        } else {
#pragma unroll
            for (int q = 0; q < 16; ++q)
                *(float4*)(dst + 4 * q) = make_float4(0.f, 0.f, 0.f, 0.f);
        }
    }
    __syncthreads();

    // phase 2: GEMM + epilogue
    int ty = tid >> 4, tx = tid & 15;
    float sum[8][8];
    gemm_8x8(P2, WP, ty, tx, sum);

#pragma unroll
    for (int i = 0; i < 8; ++i) {
        int n2 = base + ty * 8 + i;
        if (n2 >= N) continue;
#pragma unroll
        for (int jj = 0; jj < 8; ++jj) {
            int j = tx + 16 * jj;
            float v = sum[i][jj];
            if (mat == 0) {
                g_K[(size_t)n2 * CDIM + j] = __expf(fminf(v, 60.0f));
            } else if (mat == 1) {
                g_V[(size_t)n2 * CDIM + j] = v * g_w[j];
            } else {
                g_R[(size_t)n2 * CDIM + j] = __fdividef(1.0f, 1.0f + __expf(-v));
            }
        }
    }
}

// ---------------- edge kernel: p = r*(ah + k*vw)/(bh + k + eps); out = p @ Wo.T ----------------
__global__ __launch_bounds__(NTHREADS, 1)
void edge_kernel(const float* __restrict__ ah, const float* __restrict__ bh,
                 const float* __restrict__ Wo, float* __restrict__ out,
                 int E, int nTiles) {
    unsigned long long* WP = sm_dyn;
    unsigned long long* P2 = sm_dyn + (CDIM / 2) * CDIM;
    float* P2f = (float*)P2;

    fill_WP(WP, Wo);
    __syncthreads();

    int tid = threadIdx.x;
    int ty = tid >> 4, tx = tid & 15;
    int r0 = tid >> 1, half = tid & 1;

    for (int tile = blockIdx.x; tile < nTiles; tile += gridDim.x) {
        int base = tile * TILE;
        int e = base + r0;

        // phase 1: per-edge elementwise into P2
        {
            float* dst = P2f + (size_t)r0 * (SP_STRIDE * 2) + half * 64;
            if (e < E) {
                int si = g_s[e];
                int vi = g_t[e];
                const float4* a4 = (const float4*)(ah  + (size_t)e  * CDIM + half * 64);
                const float4* b4 = (const float4*)(bh  + (size_t)e  * CDIM + half * 64);
                const float4* k4 = (const float4*)(g_K + (size_t)si * CDIM + half * 64);
                const float4* v4 = (const float4*)(g_V + (size_t)vi * CDIM + half * 64);
                const float4* r4 = (const float4*)(g_R + (size_t)si * CDIM + half * 64);
#pragma unroll
                for (int q = 0; q < 16; ++q) {
                    float4 av = a4[q], bv = b4[q], kv = k4[q], vv = v4[q], rv = r4[q];
                    float4 p;
                    p.x = rv.x * __fdividef(av.x + kv.x * vv.x, bv.x + kv.x + 1e-20f);
                    p.y = rv.y * __fdividef(av.y + kv.y * vv.y, bv.y + kv.y + 1e-20f);
                    p.z = rv.z * __fdividef(av.z + kv.z * vv.z, bv.z + kv.z + 1e-20f);
                    p.w = rv.w * __fdividef(av.w + kv.w * vv.w, bv.w + kv.w + 1e-20f);
                    *(float4*)(dst + 4 * q) = p;
                }
            } else {
#pragma unroll
                for (int q = 0; q < 16; ++q)
                    *(float4*)(dst + 4 * q) = make_float4(0.f, 0.f, 0.f, 0.f);
            }
        }
        __syncthreads();

        // phase 2: out tile = P2 @ Wo^T
        float sum[8][8];
        gemm_8x8(P2, WP, ty, tx, sum);

#pragma unroll
        for (int i = 0; i < 8; ++i) {
            int e2 = base + ty * 8 + i;
            if (e2 >= E) continue;
            float* orow = out + (size_t)e2 * CDIM;
#pragma unroll
            for (int jj = 0; jj < 8; ++jj) {
                orow[tx + 16 * jj] = sum[i][jj];
            }
        }
        __syncthreads();  // before next tile overwrites P2
    }
}

// ---------------- launch ----------------
extern "C" void kernel_launch(void* const* d_in, const int* in_sizes, int n_in,
                              void* d_out, int out_size) {
    const float* x      = (const float*)d_in[0];
    const float* prev_x = (const float*)d_in[1];
    const float* ah     = (const float*)d_in[2];
    const float* bh     = (const float*)d_in[3];
    const float* Wk     = (const float*)d_in[4];
    const float* Wv     = (const float*)d_in[5];
    const float* Wr     = (const float*)d_in[6];
    const float* Wo     = (const float*)d_in[7];
    const float* tmk    = (const float*)d_in[8];
    const float* tmv    = (const float*)d_in[9];
    const float* tmr    = (const float*)d_in[10];
    const float* tw     = (const float*)d_in[11];
    const void*  s      = d_in[12];
    const void*  t      = d_in[13];
    const void*  ip     = d_in[14];
    const void*  Tp     = d_in[15];

    int N = in_sizes[0] / CDIM;
    int E = in_sizes[2] / CDIM;

    size_t smem = ((size_t)(CDIM / 2) * CDIM + (size_t)TILE * SP_STRIDE)
                  * sizeof(unsigned long long);  // 133120 B

    cudaFuncSetAttribute(node_kernel, cudaFuncAttributeMaxDynamicSharedMemorySize, (int)smem);
    cudaFuncSetAttribute(edge_kernel, cudaFuncAttributeMaxDynamicSharedMemorySize, (int)smem);

    prep_kernel<<<1, 128>>>(tw, ip, Tp, s);
    idx_kernel<<<(E + 255) / 256, 256>>>(s, t, E);

    int nNodeTiles = (N + TILE - 1) / TILE;
    dim3 ngrid(nNodeTiles, 3);
    node_kernel<<<ngrid, NTHREADS, smem>>>(x, prev_x, Wk, Wv, Wr, tmk, tmv, tmr, N);

    int nTiles = (E + TILE - 1) / TILE;
    edge_kernel<<<148, NTHREADS, smem>>>(ah, bh, Wo, (float*)d_out, E, nTiles);
}

// round 2
// speedup vs baseline: 1.3253x; 1.3253x over previous
#include <cuda_runtime.h>
#include <cstdint>

// ---------------- problem constants ----------------
#define CDIM 128
#define MAXN 25600          // N = 25000
#define MAXE 404000         // E = 400000
#define TILE 128            // rows (edges/nodes) per block tile
#define NTHREADS 256        // node kernel threads
#define ETHREADS 512        // edge kernel threads (16 warps)
#define SP_STRIDE 66        // node P2 row stride in ull units, padded

// ---------------- device scratch (no allocs allowed) ----------------
__device__ float g_K[(size_t)MAXN * CDIM];   // exp(min(k,60)) per node
__device__ float g_V[(size_t)MAXN * CDIM];   // w[c] * v per node
__device__ float g_R[(size_t)MAXN * CDIM];   // sigmoid(r) per node
__device__ float g_w[CDIM];
__device__ int   g_s[MAXE];
__device__ int   g_t[MAXE];
__device__ int   g_is64;

// ---------------- helpers ----------------
union U64F2 { unsigned long long u; float2 f; };

__device__ __forceinline__ void ffma2(unsigned long long& d,
                                      unsigned long long a,
                                      unsigned long long b) {
    asm("fma.rn.f32x2 %0, %1, %2, %3;" : "=l"(d) : "l"(a), "l"(b), "l"(d));
}

// pack two floats -> bf16x2 (lo = a, hi = b), plus residual pack
__device__ __forceinline__ void split2(float a, float b, uint32_t& h, uint32_t& l) {
    asm("cvt.rn.bf16x2.f32 %0, %1, %2;" : "=r"(h) : "f"(b), "f"(a));
    float fa = __uint_as_float(h << 16);
    float fb = __uint_as_float(h & 0xFFFF0000u);
    float ra = a - fa, rb = b - fb;
    asm("cvt.rn.bf16x2.f32 %0, %1, %2;" : "=r"(l) : "f"(rb), "f"(ra));
}

__device__ __forceinline__ void ldsm_x4(uint32_t* r, uint32_t addr) {
    asm volatile("ldmatrix.sync.aligned.m8n8.x4.shared.b16 {%0,%1,%2,%3}, [%4];"
                 : "=r"(r[0]), "=r"(r[1]), "=r"(r[2]), "=r"(r[3]) : "r"(addr));
}

__device__ __forceinline__ void mma_bf16(float* d, const uint32_t* a, const uint32_t* b) {
    asm volatile(
        "mma.sync.aligned.m16n8k16.row.col.f32.bf16.bf16.f32 "
        "{%0,%1,%2,%3}, {%4,%5,%6,%7}, {%8,%9}, {%0,%1,%2,%3};"
        : "+f"(d[0]), "+f"(d[1]), "+f"(d[2]), "+f"(d[3])
        : "r"(a[0]), "r"(a[1]), "r"(a[2]), "r"(a[3]), "r"(b[0]), "r"(b[1]));
}

// swizzled byte offset within a 128-row x 256B-row tile (16B chunks)
__device__ __forceinline__ uint32_t swz(int row, int chunk) {
    return (uint32_t)(row * 256) + (uint32_t)(((chunk ^ (row & 7)) << 4));
}

// ---------------- prep: per-channel decay w, index dtype detection ----------------
__global__ void prep_kernel(const float* __restrict__ time_w,
                            const void* ip, const void* Tp,
                            const void* sraw) {
    int c = threadIdx.x;
    if (c < CDIM) {
        int iv = *(const int*)ip;
        int Tv = *(const int*)Tp;
        float f = -(float)(Tv - iv - 1);
        g_w[c] = __expf(f * time_w[c]);
    }
    if (threadIdx.x == 0) {
        const int* w = (const int*)sraw;
        int any = 0;
#pragma unroll
        for (int k = 0; k < 64; ++k) any |= w[2 * k + 1];
        g_is64 = (any == 0) ? 1 : 0;
    }
}

__global__ void idx_kernel(const void* sraw, const void* traw, int E) {
    int e = blockIdx.x * blockDim.x + threadIdx.x;
    if (e >= E) return;
    if (g_is64) {
        g_s[e] = (int)((const long long*)sraw)[e];
        g_t[e] = (int)((const long long*)traw)[e];
    } else {
        g_s[e] = ((const int*)sraw)[e];
        g_t[e] = ((const int*)traw)[e];
    }
}

// ---------------- node kernel (FFMA2 path, unchanged) ----------------
extern __shared__ unsigned long long sm_dyn[];

__device__ __forceinline__ void gemm_8x8(const unsigned long long* __restrict__ P2,
                                         const unsigned long long* __restrict__ WP,
                                         int ty, int tx,
                                         float out_sum[8][8]) {
    unsigned long long acc[8][8];
#pragma unroll
    for (int i = 0; i < 8; ++i)
#pragma unroll
        for (int j = 0; j < 8; ++j) acc[i][j] = 0ull;

    const unsigned long long* Pr = P2 + (size_t)(ty * 8) * SP_STRIDE;

#pragma unroll 4
    for (int cp = 0; cp < CDIM / 2; ++cp) {
        unsigned long long pv[8], wv[8];
#pragma unroll
        for (int i = 0; i < 8; ++i) pv[i] = Pr[i * SP_STRIDE + cp];
#pragma unroll
        for (int jj = 0; jj < 8; ++jj) wv[jj] = WP[cp * CDIM + tx + 16 * jj];
#pragma unroll
        for (int i = 0; i < 8; ++i)
#pragma unroll
            for (int jj = 0; jj < 8; ++jj) ffma2(acc[i][jj], pv[i], wv[jj]);
    }

#pragma unroll
    for (int i = 0; i < 8; ++i)
#pragma unroll
        for (int jj = 0; jj < 8; ++jj) {
            U64F2 u; u.u = acc[i][jj];
            out_sum[i][jj] = u.f.x + u.f.y;
        }
}

__device__ __forceinline__ void fill_WP(unsigned long long* WP,
                                        const float* __restrict__ W) {
    for (int idx = threadIdx.x; idx < (CDIM / 2) * CDIM; idx += NTHREADS) {
        int cp = idx >> 7;
        int j  = idx & (CDIM - 1);
        WP[idx] = *(const unsigned long long*)(W + j * CDIM + 2 * cp);
    }
}

__global__ __launch_bounds__(NTHREADS, 1)
void node_kernel(const float* __restrict__ x, const float* __restrict__ prevx,
                 const float* __restrict__ Wk, const float* __restrict__ Wv,
                 const float* __restrict__ Wr,
                 const float* __restrict__ tmk, const float* __restrict__ tmv,
                 const float* __restrict__ tmr, int N) {
    unsigned long long* WP = sm_dyn;
    unsigned long long* P2 = sm_dyn + (CDIM / 2) * CDIM;
    float* P2f = (float*)P2;

    int mat = blockIdx.y;
    const float* W  = (mat == 0) ? Wk  : (mat == 1) ? Wv  : Wr;
    const float* tm = (mat == 0) ? tmk : (mat == 1) ? tmv : tmr;

    fill_WP(WP, W);

    int tid  = threadIdx.x;
    int r0   = tid >> 1, half = tid & 1;
    int base = blockIdx.x * TILE;
    int node = base + r0;

    {
        float* dst = P2f + (size_t)r0 * (SP_STRIDE * 2) + half * 64;
        if (node < N) {
            const float4* x4 = (const float4*)(x    + (size_t)node * CDIM + half * 64);
            const float4* p4 = (const float4*)(prevx+ (size_t)node * CDIM + half * 64);
            const float4* t4 = (const float4*)(tm + half * 64);
#pragma unroll
            for (int q = 0; q < 16; ++q) {
                float4 xv = x4[q], pv = p4[q], tv = t4[q];
                float4 m;
                m.x = pv.x + tv.x * (xv.x - pv.x);
                m.y = pv.y + tv.y * (xv.y - pv.y);
                m.z = pv.z + tv.z * (xv.z - pv.z);
                m.w = pv.w + tv.w * (xv.w - pv.w);
                *(float4*)(dst + 4 * q) = m;
            }
        } else {
#pragma unroll
            for (int q = 0; q < 16; ++q)
                *(float4*)(dst + 4 * q) = make_float4(0.f, 0.f, 0.f, 0.f);
        }
    }
    __syncthreads();

    int ty = tid >> 4, tx = tid & 15;
    float sum[8][8];
    gemm_8x8(P2, WP, ty, tx, sum);

#pragma unroll
    for (int i = 0; i < 8; ++i) {
        int n2 = base + ty * 8 + i;
        if (n2 >= N) continue;
#pragma unroll
        for (int jj = 0; jj < 8; ++jj) {
            int j = tx + 16 * jj;
            float v = sum[i][jj];
            if (mat == 0) {
                g_K[(size_t)n2 * CDIM + j] = __expf(fminf(v, 60.0f));
            } else if (mat == 1) {
                g_V[(size_t)n2 * CDIM + j] = v * g_w[j];
            } else {
                g_R[(size_t)n2 * CDIM + j] = __fdividef(1.0f, 1.0f + __expf(-v));
            }
        }
    }
}

// ---------------- edge kernel: tensor-core (bf16-split) version ----------------
// smem: Whi[128x128 bf16, swizzled 256B rows] | Wlo | Phi | Plo  = 4 x 32KB
// Warp tiling: 16 warps = 4 (m) x 4 (n); each warp: 32 rows x 32 cols
//   m-blocks of 16 (mb=0..1), n-blocks of 8 (nb=0..3)
// GEMM: out = Phi@Whi + Plo@Whi + Phi@Wlo   (fp32 accumulate)

__global__ __launch_bounds__(ETHREADS, 1)
void edge_mma_kernel(const float* __restrict__ ah, const float* __restrict__ bh,
                     const float* __restrict__ Wo, float* __restrict__ out,
                     int E, int nTiles) {
    extern __shared__ __align__(16) char sm8[];
    char* Whi = sm8;
    char* Wlo = sm8 + 32768;
    char* Phi = sm8 + 65536;
    char* Plo = sm8 + 98304;
    uint32_t sbase = (uint32_t)__cvta_generic_to_shared(sm8);
    const uint32_t sWhi = sbase;
    const uint32_t sWlo = sbase + 32768;
    const uint32_t sPhi = sbase + 65536;
    const uint32_t sPlo = sbase + 98304;

    int tid = threadIdx.x;

    // ---- fill W (split to hi/lo bf16, swizzled) ----
    for (int idx = tid; idx < 128 * 16; idx += ETHREADS) {
        int j = idx >> 4, ci = idx & 15;
        const float4* w4 = (const float4*)(Wo + (size_t)j * CDIM + ci * 8);
        float4 f0 = w4[0], f1 = w4[1];
        uint4 h, l;
        split2(f0.x, f0.y, h.x, l.x);
        split2(f0.z, f0.w, h.y, l.y);
        split2(f1.x, f1.y, h.z, l.z);
        split2(f1.z, f1.w, h.w, l.w);
        uint32_t off = swz(j, ci);
        *(uint4*)(Whi + off) = h;
        *(uint4*)(Wlo + off) = l;
    }
    __syncthreads();

    int lane = tid & 31, wid = tid >> 5;
    int warp_m = wid >> 2;          // 0..3  -> rows warp_m*32
    int warp_n = wid & 3;           // 0..3  -> cols warp_n*32

    // ldmatrix lane->address components
    int a_row0 = warp_m * 32 + (lane & 15);          // + mb*16
    int a_cb   = lane >> 4;                          // chunk offset bit
    int b_row0 = warp_n * 32 + (lane & 7) + ((lane >> 4) << 3);  // + np*16
    int b_cb   = (lane >> 3) & 1;

    // phase-1 mapping: 512 threads -> 128 rows x 4 quarters (32 cols each)
    int r0 = tid >> 2, quarter = tid & 3;

    for (int tile = blockIdx.x; tile < nTiles; tile += gridDim.x) {
        int base = tile * TILE;

        // ---- phase 1: per-edge elementwise -> split bf16 tiles ----
        {
            int e = base + r0;
            if (e < E) {
                int si = g_s[e];
                int vi = g_t[e];
                const float4* a4 = (const float4*)(ah  + (size_t)e  * CDIM);
                const float4* b4 = (const float4*)(bh  + (size_t)e  * CDIM);
                const float4* k4 = (const float4*)(g_K + (size_t)si * CDIM);
                const float4* v4 = (const float4*)(g_V + (size_t)vi * CDIM);
                const float4* r4 = (const float4*)(g_R + (size_t)si * CDIM);
#pragma unroll
                for (int cc = 0; cc < 4; ++cc) {
                    int ci = quarter * 4 + cc;     // 16B chunk index (8 floats)
                    int q0 = ci * 2;               // float4 index
                    float4 av0 = a4[q0], av1 = a4[q0 + 1];
                    float4 bv0 = b4[q0], bv1 = b4[q0 + 1];
                    float4 kv0 = k4[q0], kv1 = k4[q0 + 1];
                    float4 vv0 = v4[q0], vv1 = v4[q0 + 1];
                    float4 rv0 = r4[q0], rv1 = r4[q0 + 1];
                    float p[8];
                    p[0] = rv0.x * __fdividef(av0.x + kv0.x * vv0.x, bv0.x + kv0.x + 1e-20f);
                    p[1] = rv0.y * __fdividef(av0.y + kv0.y * vv0.y, bv0.y + kv0.y + 1e-20f);
                    p[2] = rv0.z * __fdividef(av0.z + kv0.z * vv0.z, bv0.z + kv0.z + 1e-20f);
                    p[3] = rv0.w * __fdividef(av0.w + kv0.w * vv0.w, bv0.w + kv0.w + 1e-20f);
                    p[4] = rv1.x * __fdividef(av1.x + kv1.x * vv1.x, bv1.x + kv1.x + 1e-20f);
                    p[5] = rv1.y * __fdividef(av1.y + kv1.y * vv1.y, bv1.y + kv1.y + 1e-20f);
                    p[6] = rv1.z * __fdividef(av1.z + kv1.z * vv1.z, bv1.z + kv1.z + 1e-20f);
                    p[7] = rv1.w * __fdividef(av1.w + kv1.w * vv1.w, bv1.w + kv1.w + 1e-20f);
                    uint4 h, l;
                    split2(p[0], p[1], h.x, l.x);
                    split2(p[2], p[3], h.y, l.y);
                    split2(p[4], p[5], h.z, l.z);
                    split2(p[6], p[7], h.w, l.w);
                    uint32_t off = swz(r0, ci);
                    *(uint4*)(Phi + off) = h;
                    *(uint4*)(Plo + off) = l;
                }
            } else {
                uint4 z = make_uint4(0, 0, 0, 0);
#pragma unroll
                for (int cc = 0; cc < 4; ++cc) {
                    uint32_t off = swz(r0, quarter * 4 + cc);
                    *(uint4*)(Phi + off) = z;
                    *(uint4*)(Plo + off) = z;
                }
            }
        }
        __syncthreads();

        // ---- phase 2: tensor-core GEMM ----
        float acc[2][4][4];
#pragma unroll
        for (int mb = 0; mb < 2; ++mb)
#pragma unroll
            for (int nb = 0; nb < 4; ++nb)
#pragma unroll
                for (int q = 0; q < 4; ++q) acc[mb][nb][q] = 0.f;

#pragma unroll
        for (int ks = 0; ks < 8; ++ks) {
            uint32_t Ah[2][4], Al[2][4];
#pragma unroll
            for (int mb = 0; mb < 2; ++mb) {
                int row = a_row0 + mb * 16;
                uint32_t off = swz(row, ks * 2 + a_cb);
                ldsm_x4(Ah[mb], sPhi + off);
                ldsm_x4(Al[mb], sPlo + off);
            }
#pragma unroll
            for (int np = 0; np < 2; ++np) {
                int row = b_row0 + np * 16;
                uint32_t off = swz(row, ks * 2 + b_cb);
                uint32_t Bh[4], Bl[4];
                ldsm_x4(Bh, sWhi + off);
                ldsm_x4(Bl, sWlo + off);
#pragma unroll
                for (int mb = 0; mb < 2; ++mb) {
                    mma_bf16(acc[mb][2 * np],     Ah[mb], Bh);
                    mma_bf16(acc[mb][2 * np],     Al[mb], Bh);
                    mma_bf16(acc[mb][2 * np],     Ah[mb], Bl);
                    mma_bf16(acc[mb][2 * np + 1], Ah[mb], Bh + 2);
                    mma_bf16(acc[mb][2 * np + 1], Al[mb], Bh + 2);
                    mma_bf16(acc[mb][2 * np + 1], Ah[mb], Bl + 2);
                }
            }
        }

        // ---- epilogue: store to gmem ----
#pragma unroll
        for (int mb = 0; mb < 2; ++mb) {
            int r1 = base + warp_m * 32 + mb * 16 + (lane >> 2);
            int r2 = r1 + 8;
#pragma unroll
            for (int nb = 0; nb < 4; ++nb) {
                int col = warp_n * 32 + nb * 8 + (lane & 3) * 2;
                if (r1 < E) {
                    float2 v; v.x = acc[mb][nb][0]; v.y = acc[mb][nb][1];
                    *(float2*)(out + (size_t)r1 * CDIM + col) = v;
                }
                if (r2 < E) {
                    float2 v; v.x = acc[mb][nb][2]; v.y = acc[mb][nb][3];
                    *(float2*)(out + (size_t)r2 * CDIM + col) = v;
                }
            }
        }
        __syncthreads();   // protect P tiles before next phase-1
    }
}

// ---------------- launch ----------------
extern "C" void kernel_launch(void* const* d_in, const int* in_sizes, int n_in,
                              void* d_out, int out_size) {
    const float* x      = (const float*)d_in[0];
    const float* prev_x = (const float*)d_in[1];
    const float* ah     = (const float*)d_in[2];
    const float* bh     = (const float*)d_in[3];
    const float* Wk     = (const float*)d_in[4];
    const float* Wv     = (const float*)d_in[5];
    const float* Wr     = (const float*)d_in[6];
    const float* Wo     = (const float*)d_in[7];
    const float* tmk    = (const float*)d_in[8];
    const float* tmv    = (const float*)d_in[9];
    const float* tmr    = (const float*)d_in[10];
    const float* tw     = (const float*)d_in[11];
    const void*  s      = d_in[12];
    const void*  t      = d_in[13];
    const void*  ip     = d_in[14];
    const void*  Tp     = d_in[15];

    int N = in_sizes[0] / CDIM;
    int E = in_sizes[2] / CDIM;

    size_t node_smem = ((size_t)(CDIM / 2) * CDIM + (size_t)TILE * SP_STRIDE)
                       * sizeof(unsigned long long);  // 133120 B
    size_t edge_smem = 4 * 32768;                     // 131072 B

    cudaFuncSetAttribute(node_kernel, cudaFuncAttributeMaxDynamicSharedMemorySize, (int)node_smem);
    cudaFuncSetAttribute(edge_mma_kernel, cudaFuncAttributeMaxDynamicSharedMemorySize, (int)edge_smem);

    prep_kernel<<<1, 128>>>(tw, ip, Tp, s);
    idx_kernel<<<(E + 255) / 256, 256>>>(s, t, E);

    int nNodeTiles = (N + TILE - 1) / TILE;
    dim3 ngrid(nNodeTiles, 3);
    node_kernel<<<ngrid, NTHREADS, node_smem>>>(x, prev_x, Wk, Wv, Wr, tmk, tmv, tmr, N);

    int nTiles = (E + TILE - 1) / TILE;
    edge_mma_kernel<<<148, ETHREADS, edge_smem>>>(ah, bh, Wo, (float*)d_out, E, nTiles);
}

// round 4
// speedup vs baseline: 1.5346x; 1.1579x over previous
#include <cuda_runtime.h>
#include <cstdint>

// ---------------- problem constants ----------------
#define CDIM 128
#define MAXN 25600
#define MAXE 404000
#define TILE 128
#define WSTHREADS 512       // 8 consumer warps + 8 producer warps

// ---------------- device scratch ----------------
__device__ float g_K[(size_t)MAXN * CDIM];
__device__ float g_V[(size_t)MAXN * CDIM];
__device__ float g_R[(size_t)MAXN * CDIM];
__device__ float g_w[CDIM];
__device__ int   g_s[MAXE];
__device__ int   g_t[MAXE];
__device__ int   g_is64;

// ---------------- helpers ----------------
__device__ __forceinline__ uint32_t smem_u32(const void* p) {
    return (uint32_t)__cvta_generic_to_shared(p);
}

// swizzled byte offset within a 128-row x 256B-row tile (16B chunks)
__device__ __forceinline__ uint32_t swz(int row, int chunk) {
    return (uint32_t)(row * 256) + (uint32_t)(((chunk ^ (row & 7)) << 4));
}

// pack two floats -> bf16x2 (lo=a, hi=b) + residual
__device__ __forceinline__ void split2(float a, float b, uint32_t& h, uint32_t& l) {
    asm("cvt.rn.bf16x2.f32 %0, %1, %2;" : "=r"(h) : "f"(b), "f"(a));
    float fa = __uint_as_float(h << 16);
    float fb = __uint_as_float(h & 0xFFFF0000u);
    float ra = a - fa, rb = b - fb;
    asm("cvt.rn.bf16x2.f32 %0, %1, %2;" : "=r"(l) : "f"(rb), "f"(ra));
}

__device__ __forceinline__ void split_store8(char* Hi, char* Lo, int row, int c8,
                                             const float* p) {
    uint4 h, l;
    split2(p[0], p[1], h.x, l.x);
    split2(p[2], p[3], h.y, l.y);
    split2(p[4], p[5], h.z, l.z);
    split2(p[6], p[7], h.w, l.w);
    uint32_t off = swz(row, c8);
    *(uint4*)(Hi + off) = h;
    *(uint4*)(Lo + off) = l;
}

__device__ __forceinline__ void fill_W_split(char* Whi, char* Wlo,
                                             const float* __restrict__ W,
                                             int tid, int nthreads) {
    for (int idx = tid; idx < 128 * 16; idx += nthreads) {
        int j = idx >> 4, ci = idx & 15;
        const float4* w4 = (const float4*)(W + (size_t)j * CDIM + ci * 8);
        float4 f0 = w4[0], f1 = w4[1];
        float p[8] = {f0.x, f0.y, f0.z, f0.w, f1.x, f1.y, f1.z, f1.w};
        split_store8(Whi, Wlo, j, ci, p);
    }
}

__device__ __forceinline__ void ldsm_x4(uint32_t* r, uint32_t addr) {
    asm volatile("ldmatrix.sync.aligned.m8n8.x4.shared.b16 {%0,%1,%2,%3}, [%4];"
                 : "=r"(r[0]), "=r"(r[1]), "=r"(r[2]), "=r"(r[3]) : "r"(addr));
}

__device__ __forceinline__ void mma_bf16(float* d, const uint32_t* a, const uint32_t* b) {
    asm volatile(
        "mma.sync.aligned.m16n8k16.row.col.f32.bf16.bf16.f32 "
        "{%0,%1,%2,%3}, {%4,%5,%6,%7}, {%8,%9}, {%0,%1,%2,%3};"
        : "+f"(d[0]), "+f"(d[1]), "+f"(d[2]), "+f"(d[3])
        : "r"(a[0]), "r"(a[1]), "r"(a[2]), "r"(a[3]), "r"(b[0]), "r"(b[1]));
}

__device__ __forceinline__ void mbar_init(uint32_t mbar, uint32_t cnt) {
    asm volatile("mbarrier.init.shared.b64 [%0], %1;" :: "r"(mbar), "r"(cnt) : "memory");
}
__device__ __forceinline__ void mbar_arrive(uint32_t mbar) {
    asm volatile("mbarrier.arrive.release.cta.shared::cta.b64 _, [%0];"
                 :: "r"(mbar) : "memory");
}
__device__ __forceinline__ void mbar_wait(uint32_t mbar, uint32_t parity) {
    asm volatile(
        "{\n\t.reg .pred P;\n"
        "W_%=:\n\t"
        "mbarrier.try_wait.parity.acquire.cta.shared::cta.b64 P, [%0], %1, 0x989680;\n\t"
        "@P bra.uni D_%=;\n\t"
        "bra.uni W_%=;\n"
        "D_%=:\n\t}"
        :: "r"(mbar), "r"(parity) : "memory");
}

#define BARSYNC(id) asm volatile("bar.sync %0, 256;" :: "r"(id) : "memory")

// smem: Whi 32K | Wlo 32K | Pbuf0 (hi 32K, lo 32K) | Pbuf1 (64K) | ctrl 32B
#define WS_SMEM (196608 + 64)

// ---------------- prep / idx ----------------
__global__ void prep_kernel(const float* __restrict__ time_w,
                            const void* ip, const void* Tp,
                            const void* sraw) {
    int c = threadIdx.x;
    if (c < CDIM) {
        int iv = *(const int*)ip;
        int Tv = *(const int*)Tp;
        float f = -(float)(Tv - iv - 1);
        g_w[c] = __expf(f * time_w[c]);
    }
    if (threadIdx.x == 0) {
        const int* w = (const int*)sraw;
        int any = 0;
#pragma unroll
        for (int k = 0; k < 64; ++k) any |= w[2 * k + 1];
        g_is64 = (any == 0) ? 1 : 0;
    }
}

__global__ void idx_kernel(const void* sraw, const void* traw, int E) {
    int e = blockIdx.x * blockDim.x + threadIdx.x;
    if (e >= E) return;
    if (g_is64) {
        g_s[e] = (int)((const long long*)sraw)[e];
        g_t[e] = (int)((const long long*)traw)[e];
    } else {
        g_s[e] = ((const int*)sraw)[e];
        g_t[e] = ((const int*)traw)[e];
    }
}

// ---------------- consumer GEMM core ----------------
// 8 warps: wm = wid>>2 (0..1), wn = wid&3 (0..3). Warp tile 64 rows x 32 cols.
// acc[mb 0..3][nb 0..3][4]
__device__ __forceinline__ void consumer_gemm(uint32_t sPhi, uint32_t sPlo,
                                              uint32_t sWhi, uint32_t sWlo,
                                              int wm, int wn, int lane,
                                              float acc[4][4][4]) {
#pragma unroll
    for (int mb = 0; mb < 4; ++mb)
#pragma unroll
        for (int nb = 0; nb < 4; ++nb)
#pragma unroll
            for (int q = 0; q < 4; ++q) acc[mb][nb][q] = 0.f;

    int br0 = wn * 32 + (lane & 7) + ((lane >> 4) << 3);
    int ar_base = wm * 64 + (lane & 15);
    int cb = (lane >> 3) & 1;
    int ca = lane >> 4;

#pragma unroll
    for (int ks = 0; ks < 8; ++ks) {
        uint32_t Bh0[4], Bh1[4], Bl0[4], Bl1[4];
        {
            uint32_t offb0 = swz(br0, ks * 2 + cb);
            uint32_t offb1 = swz(br0 + 16, ks * 2 + cb);
            ldsm_x4(Bh0, sWhi + offb0);
            ldsm_x4(Bl0, sWlo + offb0);
            ldsm_x4(Bh1, sWhi + offb1);
            ldsm_x4(Bl1, sWlo + offb1);
        }
#pragma unroll
        for (int h = 0; h < 2; ++h) {
            uint32_t Ah[2][4], Al[2][4];
#pragma unroll
            for (int m = 0; m < 2; ++m) {
                uint32_t offa = swz(ar_base + (h * 2 + m) * 16, ks * 2 + ca);
                ldsm_x4(Ah[m], sPhi + offa);
                ldsm_x4(Al[m], sPlo + offa);
            }
#pragma unroll
            for (int m = 0; m < 2; ++m) {
                int mb = h * 2 + m;
                mma_bf16(acc[mb][0], Ah[m], Bh0);
                mma_bf16(acc[mb][0], Al[m], Bh0);
                mma_bf16(acc[mb][0], Ah[m], Bl0);
                mma_bf16(acc[mb][1], Ah[m], Bh0 + 2);
                mma_bf16(acc[mb][1], Al[m], Bh0 + 2);
                mma_bf16(acc[mb][1], Ah[m], Bl0 + 2);
                mma_bf16(acc[mb][2], Ah[m], Bh1);
                mma_bf16(acc[mb][2], Al[m], Bh1);
                mma_bf16(acc[mb][2], Ah[m], Bl1);
                mma_bf16(acc[mb][3], Ah[m], Bh1 + 2);
                mma_bf16(acc[mb][3], Al[m], Bh1 + 2);
                mma_bf16(acc[mb][3], Ah[m], Bl1 + 2);
            }
        }
    }
}

// ================= edge kernel (warp-specialized pipeline) =================
__global__ __launch_bounds__(WSTHREADS, 1)
void edge_ws_kernel(const float* __restrict__ ah, const float* __restrict__ bh,
                    const float* __restrict__ Wo, float* __restrict__ out,
                    int E, int nTiles) {
    extern __shared__ __align__(128) char sm[];
    char* Whi = sm;
    char* Wlo = sm + 32768;
    char* Pb  = sm + 65536;                 // 2 x (Phi 32K | Plo 32K)
    uint32_t ctrl = smem_u32(sm + 196608);  // full0, full1, empty0, empty1
    uint32_t sWhi = smem_u32(Whi), sWlo = smem_u32(Wlo);
    uint32_t sP = smem_u32(Pb);

    int tid = threadIdx.x;
    int wid = tid >> 5, lane = tid & 31;

    if (tid == 0) {
        mbar_init(ctrl + 0, 1);   // full0
        mbar_init(ctrl + 8, 1);   // full1
        mbar_init(ctrl + 16, 1);  // empty0
        mbar_init(ctrl + 24, 1);  // empty1
    }
    fill_W_split(Whi, Wlo, Wo, tid, WSTHREADS);
    __syncthreads();

    if (wid >= 8) {
        // ================= producer =================
        int ptid = tid - 256;
        int r0 = ptid >> 2;           // 0..63 (rows r0 and r0+64)
        int q  = ptid & 3;            // col quarter
        uint32_t pe[2] = {0, 0};
        int it = 0;
        for (int tile = blockIdx.x; tile < nTiles; tile += gridDim.x, ++it) {
            int b = it & 1;
            if (it >= 2) { mbar_wait(ctrl + 16 + b * 8, pe[b]); pe[b] ^= 1; }
            char* Phi = Pb + b * 65536;
            char* Plo = Phi + 32768;
            int base = tile * TILE;
#pragma unroll
            for (int rr = 0; rr < 2; ++rr) {
                int row = r0 + rr * 64;
                int e = base + row;
                if (e < E) {
                    int si = g_s[e];
                    int vi = g_t[e];
                    const float4* a4 = (const float4*)(ah  + (size_t)e  * CDIM);
                    const float4* b4 = (const float4*)(bh  + (size_t)e  * CDIM);
                    const float4* k4 = (const float4*)(g_K + (size_t)si * CDIM);
                    const float4* v4 = (const float4*)(g_V + (size_t)vi * CDIM);
                    const float4* r4 = (const float4*)(g_R + (size_t)si * CDIM);
#pragma unroll
                    for (int cc = 0; cc < 4; ++cc) {
                        int ci = q * 4 + cc;
                        float4 aa = a4[2 * ci], ab = a4[2 * ci + 1];
                        float4 ba = b4[2 * ci], bb = b4[2 * ci + 1];
                        float4 ka = k4[2 * ci], kb = k4[2 * ci + 1];
                        float4 va = v4[2 * ci], vb = v4[2 * ci + 1];
                        float4 ra = r4[2 * ci], rb = r4[2 * ci + 1];
                        float p[8];
                        p[0] = ra.x * __fdividef(aa.x + ka.x * va.x, ba.x + ka.x + 1e-20f);
                        p[1] = ra.y * __fdividef(aa.y + ka.y * va.y, ba.y + ka.y + 1e-20f);
                        p[2] = ra.z * __fdividef(aa.z + ka.z * va.z, ba.z + ka.z + 1e-20f);
                        p[3] = ra.w * __fdividef(aa.w + ka.w * va.w, ba.w + ka.w + 1e-20f);
                        p[4] = rb.x * __fdividef(ab.x + kb.x * vb.x, bb.x + kb.x + 1e-20f);
                        p[5] = rb.y * __fdividef(ab.y + kb.y * vb.y, bb.y + kb.y + 1e-20f);
                        p[6] = rb.z * __fdividef(ab.z + kb.z * vb.z, bb.z + kb.z + 1e-20f);
                        p[7] = rb.w * __fdividef(ab.w + kb.w * vb.w, bb.w + kb.w + 1e-20f);
                        split_store8(Phi, Plo, row, ci, p);
                    }
                } else {
                    uint4 z = make_uint4(0, 0, 0, 0);
#pragma unroll
                    for (int cc = 0; cc < 4; ++cc) {
                        uint32_t off = swz(row, q * 4 + cc);
                        *(uint4*)(Phi + off) = z;
                        *(uint4*)(Plo + off) = z;
                    }
                }
            }
            BARSYNC(1);
            if (ptid == 0) mbar_arrive(ctrl + b * 8);   // full[b]
        }
    } else {
        // ================= consumer =================
        int wm = wid >> 2, wn = wid & 3;
        uint32_t pf[2] = {0, 0};
        int it = 0;
        for (int tile = blockIdx.x; tile < nTiles; tile += gridDim.x, ++it) {
            int b = it & 1;
            mbar_wait(ctrl + b * 8, pf[b]); pf[b] ^= 1;
            uint32_t sPhi = sP + b * 65536;
            uint32_t sPlo = sPhi + 32768;

            float acc[4][4][4];
            consumer_gemm(sPhi, sPlo, sWhi, sWlo, wm, wn, lane, acc);

            BARSYNC(2);
            if (tid == 0) mbar_arrive(ctrl + 16 + b * 8);  // empty[b]

            int base = tile * TILE;
#pragma unroll
            for (int mb = 0; mb < 4; ++mb) {
                int rA = base + wm * 64 + mb * 16 + (lane >> 2);
                int rB = rA + 8;
#pragma unroll
                for (int nb = 0; nb < 4; ++nb) {
                    int col = wn * 32 + nb * 8 + (lane & 3) * 2;
                    if (rA < E) {
                        float2 v; v.x = acc[mb][nb][0]; v.y = acc[mb][nb][1];
                        *(float2*)(out + (size_t)rA * CDIM + col) = v;
                    }
                    if (rB < E) {
                        float2 v; v.x = acc[mb][nb][2]; v.y = acc[mb][nb][3];
                        *(float2*)(out + (size_t)rB * CDIM + col) = v;
                    }
                }
            }
        }
    }
}

// ================= node kernel (same pipeline, fused epilogues) =================
__global__ __launch_bounds__(WSTHREADS, 1)
void node_ws_kernel(const float* __restrict__ x, const float* __restrict__ prevx,
                    const float* __restrict__ Wk, const float* __restrict__ Wv,
                    const float* __restrict__ Wr,
                    const float* __restrict__ tmk, const float* __restrict__ tmv,
                    const float* __restrict__ tmr, int N, int nTiles) {
    extern __shared__ __align__(128) char sm[];
    char* Whi = sm;
    char* Wlo = sm + 32768;
    char* Pb  = sm + 65536;
    uint32_t ctrl = smem_u32(sm + 196608);
    uint32_t sWhi = smem_u32(Whi), sWlo = smem_u32(Wlo);
    uint32_t sP = smem_u32(Pb);

    int tid = threadIdx.x;
    int wid = tid >> 5, lane = tid & 31;
    int mat = blockIdx.y;
    const float* W  = (mat == 0) ? Wk  : (mat == 1) ? Wv  : Wr;
    const float* tm = (mat == 0) ? tmk : (mat == 1) ? tmv : tmr;
    float* dstG = (mat == 0) ? g_K : (mat == 1) ? g_V : g_R;

    if (tid == 0) {
        mbar_init(ctrl + 0, 1);
        mbar_init(ctrl + 8, 1);
        mbar_init(ctrl + 16, 1);
        mbar_init(ctrl + 24, 1);
    }
    fill_W_split(Whi, Wlo, W, tid, WSTHREADS);
    __syncthreads();

    if (wid >= 8) {
        int ptid = tid - 256;
        int r0 = ptid >> 2;
        int q  = ptid & 3;
        uint32_t pe[2] = {0, 0};
        int it = 0;
        for (int tile = blockIdx.x; tile < nTiles; tile += gridDim.x, ++it) {
            int b = it & 1;
            if (it >= 2) { mbar_wait(ctrl + 16 + b * 8, pe[b]); pe[b] ^= 1; }
            char* Phi = Pb + b * 65536;
            char* Plo = Phi + 32768;
            int base = tile * TILE;
#pragma unroll
            for (int rr = 0; rr < 2; ++rr) {
                int row = r0 + rr * 64;
                int node = base + row;
                if (node < N) {
                    const float4* x4 = (const float4*)(x     + (size_t)node * CDIM);
                    const float4* p4 = (const float4*)(prevx + (size_t)node * CDIM);
                    const float4* t4 = (const float4*)tm;
#pragma unroll
                    for (int cc = 0; cc < 4; ++cc) {
                        int ci = q * 4 + cc;
                        float4 xa = x4[2 * ci], xb = x4[2 * ci + 1];
                        float4 pa = p4[2 * ci], pb = p4[2 * ci + 1];
                        float4 ta = t4[2 * ci], tb = t4[2 * ci + 1];
                        float p[8];
                        p[0] = pa.x + ta.x * (xa.x - pa.x);
                        p[1] = pa.y + ta.y * (xa.y - pa.y);
                        p[2] = pa.z + ta.z * (xa.z - pa.z);
                        p[3] = pa.w + ta.w * (xa.w - pa.w);
                        p[4] = pb.x + tb.x * (xb.x - pb.x);
                        p[5] = pb.y + tb.y * (xb.y - pb.y);
                        p[6] = pb.z + tb.z * (xb.z - pb.z);
                        p[7] = pb.w + tb.w * (xb.w - pb.w);
                        split_store8(Phi, Plo, row, ci, p);
                    }
                } else {
                    uint4 z = make_uint4(0, 0, 0, 0);
#pragma unroll
                    for (int cc = 0; cc < 4; ++cc) {
                        uint32_t off = swz(row, q * 4 + cc);
                        *(uint4*)(Phi + off) = z;
                        *(uint4*)(Plo + off) = z;
                    }
                }
            }
            BARSYNC(1);
            if (ptid == 0) mbar_arrive(ctrl + b * 8);
        }
    } else {
        int wm = wid >> 2, wn = wid & 3;
        uint32_t pf[2] = {0, 0};
        int it = 0;
        for (int tile = blockIdx.x; tile < nTiles; tile += gridDim.x, ++it) {
            int b = it & 1;
            mbar_wait(ctrl + b * 8, pf[b]); pf[b] ^= 1;
            uint32_t sPhi = sP + b * 65536;
            uint32_t sPlo = sPhi + 32768;

            float acc[4][4][4];
            consumer_gemm(sPhi, sPlo, sWhi, sWlo, wm, wn, lane, acc);

            BARSYNC(2);
            if (tid == 0) mbar_arrive(ctrl + 16 + b * 8);

            int base = tile * TILE;
#pragma unroll
            for (int mb = 0; mb < 4; ++mb) {
                int rA = base + wm * 64 + mb * 16 + (lane >> 2);
                int rB = rA + 8;
#pragma unroll
                for (int nb = 0; nb < 4; ++nb) {
                    int col = wn * 32 + nb * 8 + (lane & 3) * 2;
#pragma unroll
                    for (int hh = 0; hh < 2; ++hh) {
                        int row = hh ? rB : rA;
                        if (row >= N) continue;
                        float v0 = acc[mb][nb][hh * 2];
                        float v1 = acc[mb][nb][hh * 2 + 1];
                        float2 v;
                        if (mat == 0) {
                            v.x = __expf(fminf(v0, 60.0f));
                            v.y = __expf(fminf(v1, 60.0f));
                        } else if (mat == 1) {
                            v.x = v0 * g_w[col];
                            v.y = v1 * g_w[col + 1];
                        } else {
                            v.x = __fdividef(1.0f, 1.0f + __expf(-v0));
                            v.y = __fdividef(1.0f, 1.0f + __expf(-v1));
                        }
                        *(float2*)(dstG + (size_t)row * CDIM + col) = v;
                    }
                }
            }
        }
    }
}

// ---------------- launch ----------------
extern "C" void kernel_launch(void* const* d_in, const int* in_sizes, int n_in,
                              void* d_out, int out_size) {
    const float* x      = (const float*)d_in[0];
    const float* prev_x = (const float*)d_in[1];
    const float* ah     = (const float*)d_in[2];
    const float* bh     = (const float*)d_in[3];
    const float* Wk     = (const float*)d_in[4];
    const float* Wv     = (const float*)d_in[5];
    const float* Wr     = (const float*)d_in[6];
    const float* Wo     = (const float*)d_in[7];
    const float* tmk    = (const float*)d_in[8];
    const float* tmv    = (const float*)d_in[9];
    const float* tmr    = (const float*)d_in[10];
    const float* tw     = (const float*)d_in[11];
    const void*  s      = d_in[12];
    const void*  t      = d_in[13];
    const void*  ip     = d_in[14];
    const void*  Tp     = d_in[15];

    int N = in_sizes[0] / CDIM;
    int E = in_sizes[2] / CDIM;

    cudaFuncSetAttribute(edge_ws_kernel, cudaFuncAttributeMaxDynamicSharedMemorySize, WS_SMEM);
    cudaFuncSetAttribute(node_ws_kernel, cudaFuncAttributeMaxDynamicSharedMemorySize, WS_SMEM);

    prep_kernel<<<1, 128>>>(tw, ip, Tp, s);
    idx_kernel<<<(E + 255) / 256, 256>>>(s, t, E);

    int nTilesN = (N + TILE - 1) / TILE;
    dim3 ngrid(49, 3);
    node_ws_kernel<<<ngrid, WSTHREADS, WS_SMEM>>>(x, prev_x, Wk, Wv, Wr,
                                                  tmk, tmv, tmr, N, nTilesN);

    int nTiles = (E + TILE - 1) / TILE;
    edge_ws_kernel<<<148, WSTHREADS, WS_SMEM>>>(ah, bh, Wo, (float*)d_out, E, nTiles);
}

// round 5
// speedup vs baseline: 1.8296x; 1.1923x over previous
#include <cuda_runtime.h>
#include <cstdint>

// ---------------- problem constants ----------------
#define CDIM 128
#define MAXN 25600
#define MAXE 404000
#define TILE 128
#define WSTHREADS 512       // 8 consumer warps + 8 producer warps

// ---------------- device scratch ----------------
__device__ float g_K[(size_t)MAXN * CDIM];
__device__ float g_V[(size_t)MAXN * CDIM];
__device__ float g_R[(size_t)MAXN * CDIM];
__device__ float g_w[CDIM];
__device__ int   g_s[MAXE];
__device__ int   g_t[MAXE];
__device__ int   g_is64;

// ---------------- helpers ----------------
__device__ __forceinline__ uint32_t smem_u32(const void* p) {
    return (uint32_t)__cvta_generic_to_shared(p);
}

// swizzled byte offset within a 128-row x 256B-row tile (16B chunks)
__device__ __forceinline__ uint32_t swz(int row, int chunk) {
    return (uint32_t)(row * 256) + (uint32_t)(((chunk ^ (row & 7)) << 4));
}

// pack two floats -> bf16x2 (lo=a, hi=b) + residual
__device__ __forceinline__ void split2(float a, float b, uint32_t& h, uint32_t& l) {
    asm("cvt.rn.bf16x2.f32 %0, %1, %2;" : "=r"(h) : "f"(b), "f"(a));
    float fa = __uint_as_float(h << 16);
    float fb = __uint_as_float(h & 0xFFFF0000u);
    float ra = a - fa, rb = b - fb;
    asm("cvt.rn.bf16x2.f32 %0, %1, %2;" : "=r"(l) : "f"(rb), "f"(ra));
}

__device__ __forceinline__ void fill_W_split(char* Whi, char* Wlo,
                                             const float* __restrict__ W,
                                             int tid, int nthreads) {
    for (int idx = tid; idx < 128 * 16; idx += nthreads) {
        int j = idx >> 4, ci = idx & 15;
        const float4* w4 = (const float4*)(W + (size_t)j * CDIM + ci * 8);
        float4 f0 = w4[0], f1 = w4[1];
        uint4 h, l;
        split2(f0.x, f0.y, h.x, l.x);
        split2(f0.z, f0.w, h.y, l.y);
        split2(f1.x, f1.y, h.z, l.z);
        split2(f1.z, f1.w, h.w, l.w);
        uint32_t off = swz(j, ci);
        *(uint4*)(Whi + off) = h;
        *(uint4*)(Wlo + off) = l;
    }
}

__device__ __forceinline__ void ldsm_x4(uint32_t* r, uint32_t addr) {
    asm volatile("ldmatrix.sync.aligned.m8n8.x4.shared.b16 {%0,%1,%2,%3}, [%4];"
                 : "=r"(r[0]), "=r"(r[1]), "=r"(r[2]), "=r"(r[3]) : "r"(addr));
}

__device__ __forceinline__ void mma_bf16(float* d, const uint32_t* a, const uint32_t* b) {
    asm volatile(
        "mma.sync.aligned.m16n8k16.row.col.f32.bf16.bf16.f32 "
        "{%0,%1,%2,%3}, {%4,%5,%6,%7}, {%8,%9}, {%0,%1,%2,%3};"
        : "+f"(d[0]), "+f"(d[1]), "+f"(d[2]), "+f"(d[3])
        : "r"(a[0]), "r"(a[1]), "r"(a[2]), "r"(a[3]), "r"(b[0]), "r"(b[1]));
}

__device__ __forceinline__ void mbar_init(uint32_t mbar, uint32_t cnt) {
    asm volatile("mbarrier.init.shared.b64 [%0], %1;" :: "r"(mbar), "r"(cnt) : "memory");
}
__device__ __forceinline__ void mbar_arrive(uint32_t mbar) {
    asm volatile("mbarrier.arrive.release.cta.shared::cta.b64 _, [%0];"
                 :: "r"(mbar) : "memory");
}
__device__ __forceinline__ void mbar_wait(uint32_t mbar, uint32_t parity) {
    asm volatile(
        "{\n\t.reg .pred P;\n"
        "W_%=:\n\t"
        "mbarrier.try_wait.parity.acquire.cta.shared::cta.b64 P, [%0], %1, 0x989680;\n\t"
        "@P bra.uni D_%=;\n\t"
        "bra.uni W_%=;\n"
        "D_%=:\n\t}"
        :: "r"(mbar), "r"(parity) : "memory");
}

#define BARSYNC(id) asm volatile("bar.sync %0, 256;" :: "r"(id) : "memory")

// smem: Whi 32K | Wlo 32K | Pbuf0 (hi 32K, lo 32K) | Pbuf1 (64K) | ctrl
#define WS_SMEM (196608 + 64)

// ---------------- prep / idx ----------------
__global__ void prep_kernel(const float* __restrict__ time_w,
                            const void* ip, const void* Tp,
                            const void* sraw) {
    int c = threadIdx.x;
    if (c < CDIM) {
        int iv = *(const int*)ip;
        int Tv = *(const int*)Tp;
        float f = -(float)(Tv - iv - 1);
        g_w[c] = __expf(f * time_w[c]);
    }
    if (threadIdx.x == 0) {
        const int* w = (const int*)sraw;
        int any = 0;
#pragma unroll
        for (int k = 0; k < 64; ++k) any |= w[2 * k + 1];
        g_is64 = (any == 0) ? 1 : 0;
    }
}

__global__ void idx_kernel(const void* sraw, const void* traw, int E) {
    int e = blockIdx.x * blockDim.x + threadIdx.x;
    if (e >= E) return;
    if (g_is64) {
        g_s[e] = (int)((const long long*)sraw)[e];
        g_t[e] = (int)((const long long*)traw)[e];
    } else {
        g_s[e] = ((const int*)sraw)[e];
        g_t[e] = ((const int*)traw)[e];
    }
}

// ---------------- producer row store: lane l owns channels [4l, 4l+4) ----------------
__device__ __forceinline__ void prod_store_row(char* Phi, char* Plo, int row, int lane,
                                               float p0, float p1, float p2, float p3) {
    uint32_t h0, l0, h1, l1;
    split2(p0, p1, h0, l0);
    split2(p2, p3, h1, l1);
    uint32_t off = swz(row, lane >> 1) + (lane & 1) * 8;
    uint2 h; h.x = h0; h.y = h1;
    uint2 l; l.x = l0; l.y = l1;
    *(uint2*)(Phi + off) = h;
    *(uint2*)(Plo + off) = l;
}

// ---------------- consumer GEMM core (8 warps, 64x32 warp tile) ----------------
__device__ __forceinline__ void consumer_gemm(uint32_t sPhi, uint32_t sPlo,
                                              uint32_t sWhi, uint32_t sWlo,
                                              int wm, int wn, int lane,
                                              float acc[4][4][4]) {
#pragma unroll
    for (int mb = 0; mb < 4; ++mb)
#pragma unroll
        for (int nb = 0; nb < 4; ++nb)
#pragma unroll
            for (int q = 0; q < 4; ++q) acc[mb][nb][q] = 0.f;

    int br0 = wn * 32 + (lane & 7) + ((lane >> 4) << 3);
    int ar_base = wm * 64 + (lane & 15);
    int cb = (lane >> 3) & 1;
    int ca = lane >> 4;

#pragma unroll
    for (int ks = 0; ks < 8; ++ks) {
        uint32_t Bh0[4], Bh1[4], Bl0[4], Bl1[4];
        {
            uint32_t offb0 = swz(br0, ks * 2 + cb);
            uint32_t offb1 = swz(br0 + 16, ks * 2 + cb);
            ldsm_x4(Bh0, sWhi + offb0);
            ldsm_x4(Bl0, sWlo + offb0);
            ldsm_x4(Bh1, sWhi + offb1);
            ldsm_x4(Bl1, sWlo + offb1);
        }
#pragma unroll
        for (int h = 0; h < 2; ++h) {
            uint32_t Ah[2][4], Al[2][4];
#pragma unroll
            for (int m = 0; m < 2; ++m) {
                uint32_t offa = swz(ar_base + (h * 2 + m) * 16, ks * 2 + ca);
                ldsm_x4(Ah[m], sPhi + offa);
                ldsm_x4(Al[m], sPlo + offa);
            }
#pragma unroll
            for (int m = 0; m < 2; ++m) {
                int mb = h * 2 + m;
                mma_bf16(acc[mb][0], Ah[m], Bh0);
                mma_bf16(acc[mb][0], Al[m], Bh0);
                mma_bf16(acc[mb][0], Ah[m], Bl0);
                mma_bf16(acc[mb][1], Ah[m], Bh0 + 2);
                mma_bf16(acc[mb][1], Al[m], Bh0 + 2);
                mma_bf16(acc[mb][1], Ah[m], Bl0 + 2);
                mma_bf16(acc[mb][2], Ah[m], Bh1);
                mma_bf16(acc[mb][2], Al[m], Bh1);
                mma_bf16(acc[mb][2], Ah[m], Bl1);
                mma_bf16(acc[mb][3], Ah[m], Bh1 + 2);
                mma_bf16(acc[mb][3], Al[m], Bh1 + 2);
                mma_bf16(acc[mb][3], Ah[m], Bl1 + 2);
            }
        }
    }
}

// ================= edge kernel =================
__global__ __launch_bounds__(WSTHREADS, 1)
void edge_ws_kernel(const float* __restrict__ ah, const float* __restrict__ bh,
                    const float* __restrict__ Wo, float* __restrict__ out,
                    int E, int nTiles) {
    extern __shared__ __align__(128) char sm[];
    char* Whi = sm;
    char* Wlo = sm + 32768;
    char* Pb  = sm + 65536;
    uint32_t ctrl = smem_u32(sm + 196608);  // full0, full1, empty0, empty1
    uint32_t sWhi = smem_u32(Whi), sWlo = smem_u32(Wlo);
    uint32_t sP = smem_u32(Pb);

    int tid = threadIdx.x;
    int wid = tid >> 5, lane = tid & 31;

    if (tid == 0) {
        mbar_init(ctrl + 0, 1);
        mbar_init(ctrl + 8, 1);
        mbar_init(ctrl + 16, 1);
        mbar_init(ctrl + 24, 1);
    }
    fill_W_split(Whi, Wlo, Wo, tid, WSTHREADS);
    __syncthreads();

    if (wid >= 8) {
        // ================= producer: one row per warp-instruction =================
        int pw = wid - 8;           // 0..7
        uint32_t pe[2] = {0, 0};
        int it = 0;
        for (int tile = blockIdx.x; tile < nTiles; tile += gridDim.x, ++it) {
            int b = it & 1;
            if (it >= 2) { mbar_wait(ctrl + 16 + b * 8, pe[b]); pe[b] ^= 1; }
            char* Phi = Pb + b * 65536;
            char* Plo = Phi + 32768;
            int base = tile * TILE;
#pragma unroll 2
            for (int i = 0; i < 16; ++i) {
                int row = pw + 8 * i;
                int e = base + row;
                if (e < E) {
                    int si = g_s[e];
                    int vi = g_t[e];
                    float4 av = __ldcs((const float4*)(ah) + (size_t)e * 32 + lane);
                    float4 bv = __ldcs((const float4*)(bh) + (size_t)e * 32 + lane);
                    float4 kv = *((const float4*)(g_K) + (size_t)si * 32 + lane);
                    float4 vv = *((const float4*)(g_V) + (size_t)vi * 32 + lane);
                    float4 rv = *((const float4*)(g_R) + (size_t)si * 32 + lane);
                    float p0 = rv.x * __fdividef(av.x + kv.x * vv.x, bv.x + kv.x + 1e-20f);
                    float p1 = rv.y * __fdividef(av.y + kv.y * vv.y, bv.y + kv.y + 1e-20f);
                    float p2 = rv.z * __fdividef(av.z + kv.z * vv.z, bv.z + kv.z + 1e-20f);
                    float p3 = rv.w * __fdividef(av.w + kv.w * vv.w, bv.w + kv.w + 1e-20f);
                    prod_store_row(Phi, Plo, row, lane, p0, p1, p2, p3);
                } else {
                    prod_store_row(Phi, Plo, row, lane, 0.f, 0.f, 0.f, 0.f);
                }
            }
            BARSYNC(1);
            if (tid == 256) mbar_arrive(ctrl + b * 8);   // full[b]
        }
    } else {
        // ================= consumer =================
        int wm = wid >> 2, wn = wid & 3;
        uint32_t pf[2] = {0, 0};
        int it = 0;
        for (int tile = blockIdx.x; tile < nTiles; tile += gridDim.x, ++it) {
            int b = it & 1;
            mbar_wait(ctrl + b * 8, pf[b]); pf[b] ^= 1;
            uint32_t sPhi = sP + b * 65536;
            uint32_t sPlo = sPhi + 32768;

            float acc[4][4][4];
            consumer_gemm(sPhi, sPlo, sWhi, sWlo, wm, wn, lane, acc);

            BARSYNC(2);
            if (tid == 0) mbar_arrive(ctrl + 16 + b * 8);  // empty[b]

            int base = tile * TILE;
#pragma unroll
            for (int mb = 0; mb < 4; ++mb) {
                int rA = base + wm * 64 + mb * 16 + (lane >> 2);
                int rB = rA + 8;
#pragma unroll
                for (int nb = 0; nb < 4; ++nb) {
                    int col = wn * 32 + nb * 8 + (lane & 3) * 2;
                    if (rA < E) {
                        float2 v; v.x = acc[mb][nb][0]; v.y = acc[mb][nb][1];
                        __stcs((float2*)(out + (size_t)rA * CDIM + col), v);
                    }
                    if (rB < E) {
                        float2 v; v.x = acc[mb][nb][2]; v.y = acc[mb][nb][3];
                        __stcs((float2*)(out + (size_t)rB * CDIM + col), v);
                    }
                }
            }
        }
    }
}

// ================= node kernel =================
__global__ __launch_bounds__(WSTHREADS, 1)
void node_ws_kernel(const float* __restrict__ x, const float* __restrict__ prevx,
                    const float* __restrict__ Wk, const float* __restrict__ Wv,
                    const float* __restrict__ Wr,
                    const float* __restrict__ tmk, const float* __restrict__ tmv,
                    const float* __restrict__ tmr, int N, int nTiles) {
    extern __shared__ __align__(128) char sm[];
    char* Whi = sm;
    char* Wlo = sm + 32768;
    char* Pb  = sm + 65536;
    uint32_t ctrl = smem_u32(sm + 196608);
    uint32_t sWhi = smem_u32(Whi), sWlo = smem_u32(Wlo);
    uint32_t sP = smem_u32(Pb);

    int tid = threadIdx.x;
    int wid = tid >> 5, lane = tid & 31;
    int mat = blockIdx.y;
    const float* W  = (mat == 0) ? Wk  : (mat == 1) ? Wv  : Wr;
    const float* tm = (mat == 0) ? tmk : (mat == 1) ? tmv : tmr;
    float* dstG = (mat == 0) ? g_K : (mat == 1) ? g_V : g_R;

    if (tid == 0) {
        mbar_init(ctrl + 0, 1);
        mbar_init(ctrl + 8, 1);
        mbar_init(ctrl + 16, 1);
        mbar_init(ctrl + 24, 1);
    }
    fill_W_split(Whi, Wlo, W, tid, WSTHREADS);
    __syncthreads();

    if (wid >= 8) {
        int pw = wid - 8;
        float4 tv = *((const float4*)tm + lane);
        uint32_t pe[2] = {0, 0};
        int it = 0;
        for (int tile = blockIdx.x; tile < nTiles; tile += gridDim.x, ++it) {
            int b = it & 1;
            if (it >= 2) { mbar_wait(ctrl + 16 + b * 8, pe[b]); pe[b] ^= 1; }
            char* Phi = Pb + b * 65536;
            char* Plo = Phi + 32768;
            int base = tile * TILE;
#pragma unroll 2
            for (int i = 0; i < 16; ++i) {
                int row = pw + 8 * i;
                int node = base + row;
                if (node < N) {
                    float4 xv = *((const float4*)(x)     + (size_t)node * 32 + lane);
                    float4 pv = *((const float4*)(prevx) + (size_t)node * 32 + lane);
                    float p0 = pv.x + tv.x * (xv.x - pv.x);
                    float p1 = pv.y + tv.y * (xv.y - pv.y);
                    float p2 = pv.z + tv.z * (xv.z - pv.z);
                    float p3 = pv.w + tv.w * (xv.w - pv.w);
                    prod_store_row(Phi, Plo, row, lane, p0, p1, p2, p3);
                } else {
                    prod_store_row(Phi, Plo, row, lane, 0.f, 0.f, 0.f, 0.f);
                }
            }
            BARSYNC(1);
            if (tid == 256) mbar_arrive(ctrl + b * 8);
        }
    } else {
        int wm = wid >> 2, wn = wid & 3;
        // preload decay weights for this thread's columns (mat==1)
        float wreg[4][2];
        if (mat == 1) {
#pragma unroll
            for (int nb = 0; nb < 4; ++nb) {
                int col = wn * 32 + nb * 8 + (lane & 3) * 2;
                wreg[nb][0] = g_w[col];
                wreg[nb][1] = g_w[col + 1];
            }
        }
        uint32_t pf[2] = {0, 0};
        int it = 0;
        for (int tile = blockIdx.x; tile < nTiles; tile += gridDim.x, ++it) {
            int b = it & 1;
            mbar_wait(ctrl + b * 8, pf[b]); pf[b] ^= 1;
            uint32_t sPhi = sP + b * 65536;
            uint32_t sPlo = sPhi + 32768;

            float acc[4][4][4];
            consumer_gemm(sPhi, sPlo, sWhi, sWlo, wm, wn, lane, acc);

            BARSYNC(2);
            if (tid == 0) mbar_arrive(ctrl + 16 + b * 8);

            int base = tile * TILE;
#pragma unroll
            for (int mb = 0; mb < 4; ++mb) {
                int rA = base + wm * 64 + mb * 16 + (lane >> 2);
#pragma unroll
                for (int nb = 0; nb < 4; ++nb) {
                    int col = wn * 32 + nb * 8 + (lane & 3) * 2;
#pragma unroll
                    for (int hh = 0; hh < 2; ++hh) {
                        int row = rA + hh * 8;
                        if (row >= N) continue;
                        float v0 = acc[mb][nb][hh * 2];
                        float v1 = acc[mb][nb][hh * 2 + 1];
                        float2 v;
                        if (mat == 0) {
                            v.x = __expf(fminf(v0, 60.0f));
                            v.y = __expf(fminf(v1, 60.0f));
                        } else if (mat == 1) {
                            v.x = v0 * wreg[nb][0];
                            v.y = v1 * wreg[nb][1];
                        } else {
                            v.x = __fdividef(1.0f, 1.0f + __expf(-v0));
                            v.y = __fdividef(1.0f, 1.0f + __expf(-v1));
                        }
                        *(float2*)(dstG + (size_t)row * CDIM + col) = v;
                    }
                }
            }
        }
    }
}

// ---------------- launch ----------------
extern "C" void kernel_launch(void* const* d_in, const int* in_sizes, int n_in,
                              void* d_out, int out_size) {
    const float* x      = (const float*)d_in[0];
    const float* prev_x = (const float*)d_in[1];
    const float* ah     = (const float*)d_in[2];
    const float* bh     = (const float*)d_in[3];
    const float* Wk     = (const float*)d_in[4];
    const float* Wv     = (const float*)d_in[5];
    const float* Wr     = (const float*)d_in[6];
    const float* Wo     = (const float*)d_in[7];
    const float* tmk    = (const float*)d_in[8];
    const float* tmv    = (const float*)d_in[9];
    const float* tmr    = (const float*)d_in[10];
    const float* tw     = (const float*)d_in[11];
    const void*  s      = d_in[12];
    const void*  t      = d_in[13];
    const void*  ip     = d_in[14];
    const void*  Tp     = d_in[15];

    int N = in_sizes[0] / CDIM;
    int E = in_sizes[2] / CDIM;

    cudaFuncSetAttribute(edge_ws_kernel, cudaFuncAttributeMaxDynamicSharedMemorySize, WS_SMEM);
    cudaFuncSetAttribute(node_ws_kernel, cudaFuncAttributeMaxDynamicSharedMemorySize, WS_SMEM);

    prep_kernel<<<1, 128>>>(tw, ip, Tp, s);
    idx_kernel<<<(E + 255) / 256, 256>>>(s, t, E);

    int nTilesN = (N + TILE - 1) / TILE;
    dim3 ngrid(49, 3);
    node_ws_kernel<<<ngrid, WSTHREADS, WS_SMEM>>>(x, prev_x, Wk, Wv, Wr,
                                                  tmk, tmv, tmr, N, nTilesN);

    int nTiles = (E + TILE - 1) / TILE;
    edge_ws_kernel<<<148, WSTHREADS, WS_SMEM>>>(ah, bh, Wo, (float*)d_out, E, nTiles);
}

// round 6
// speedup vs baseline: 2.8439x; 1.5543x over previous
#include <cuda_runtime.h>
#include <cstdint>

// ---------------- problem constants ----------------
#define CDIM 128
#define MAXN 25600
#define MAXE 404000
#define TILE 128
#define WSTHREADS 512       // 8 consumer warps + 8 producer warps

// ---------------- device scratch ----------------
__device__ float g_K[(size_t)MAXN * CDIM];
__device__ float g_V[(size_t)MAXN * CDIM];
__device__ float g_R[(size_t)MAXN * CDIM];
__device__ float g_w[CDIM];
__device__ int   g_s[MAXE];
__device__ int   g_t[MAXE];
__device__ int   g_is64;

// ---------------- helpers ----------------
__device__ __forceinline__ uint32_t smem_u32(const void* p) {
    return (uint32_t)__cvta_generic_to_shared(p);
}

// swizzled byte offset within a 128-row x 256B-row tile (16B chunks)
__device__ __forceinline__ uint32_t swz(int row, int chunk) {
    return (uint32_t)(row * 256) + (uint32_t)(((chunk ^ (row & 7)) << 4));
}

// pack two floats -> bf16x2 (lo=a, hi=b) + residual
__device__ __forceinline__ void split2(float a, float b, uint32_t& h, uint32_t& l) {
    asm("cvt.rn.bf16x2.f32 %0, %1, %2;" : "=r"(h) : "f"(b), "f"(a));
    float fa = __uint_as_float(h << 16);
    float fb = __uint_as_float(h & 0xFFFF0000u);
    float ra = a - fa, rb = b - fb;
    asm("cvt.rn.bf16x2.f32 %0, %1, %2;" : "=r"(l) : "f"(rb), "f"(ra));
}

__device__ __forceinline__ void fill_W_split(char* Whi, char* Wlo,
                                             const float* __restrict__ W,
                                             int tid, int nthreads) {
    for (int idx = tid; idx < 128 * 16; idx += nthreads) {
        int j = idx >> 4, ci = idx & 15;
        const float4* w4 = (const float4*)(W + (size_t)j * CDIM + ci * 8);
        float4 f0 = w4[0], f1 = w4[1];
        uint4 h, l;
        split2(f0.x, f0.y, h.x, l.x);
        split2(f0.z, f0.w, h.y, l.y);
        split2(f1.x, f1.y, h.z, l.z);
        split2(f1.z, f1.w, h.w, l.w);
        uint32_t off = swz(j, ci);
        *(uint4*)(Whi + off) = h;
        *(uint4*)(Wlo + off) = l;
    }
}

__device__ __forceinline__ void ldsm_x4(uint32_t* r, uint32_t addr) {
    asm volatile("ldmatrix.sync.aligned.m8n8.x4.shared.b16 {%0,%1,%2,%3}, [%4];"
                 : "=r"(r[0]), "=r"(r[1]), "=r"(r[2]), "=r"(r[3]) : "r"(addr));
}

__device__ __forceinline__ void mma_bf16(float* d, const uint32_t* a, const uint32_t* b) {
    asm volatile(
        "mma.sync.aligned.m16n8k16.row.col.f32.bf16.bf16.f32 "
        "{%0,%1,%2,%3}, {%4,%5,%6,%7}, {%8,%9}, {%0,%1,%2,%3};"
        : "+f"(d[0]), "+f"(d[1]), "+f"(d[2]), "+f"(d[3])
        : "r"(a[0]), "r"(a[1]), "r"(a[2]), "r"(a[3]), "r"(b[0]), "r"(b[1]));
}

__device__ __forceinline__ void mbar_init(uint32_t mbar, uint32_t cnt) {
    asm volatile("mbarrier.init.shared.b64 [%0], %1;" :: "r"(mbar), "r"(cnt) : "memory");
}
__device__ __forceinline__ void mbar_arrive(uint32_t mbar) {
    asm volatile("mbarrier.arrive.release.cta.shared::cta.b64 _, [%0];"
                 :: "r"(mbar) : "memory");
}
__device__ __forceinline__ void mbar_wait(uint32_t mbar, uint32_t parity) {
    asm volatile(
        "{\n\t.reg .pred P;\n"
        "W_%=:\n\t"
        "mbarrier.try_wait.parity.acquire.cta.shared::cta.b64 P, [%0], %1, 0x989680;\n\t"
        "@P bra.uni D_%=;\n\t"
        "bra.uni W_%=;\n"
        "D_%=:\n\t}"
        :: "r"(mbar), "r"(parity) : "memory");
}

#define BARSYNC(id) asm volatile("bar.sync %0, 256;" :: "r"(id) : "memory")

// smem: Whi 32K | Wlo 32K | Pbuf0 (hi 32K, lo 32K) | Pbuf1 (64K) | ctrl
#define WS_SMEM (196608 + 64)

// ---------------- prep / idx ----------------
__global__ void prep_kernel(const float* __restrict__ time_w,
                            const void* ip, const void* Tp,
                            const void* sraw) {
    int c = threadIdx.x;
    if (c < CDIM) {
        int iv = *(const int*)ip;
        int Tv = *(const int*)Tp;
        float f = -(float)(Tv - iv - 1);
        g_w[c] = __expf(f * time_w[c]);
    }
    if (threadIdx.x == 0) {
        const int* w = (const int*)sraw;
        int any = 0;
#pragma unroll
        for (int k = 0; k < 64; ++k) any |= w[2 * k + 1];
        g_is64 = (any == 0) ? 1 : 0;
    }
}

__global__ void idx_kernel(const void* sraw, const void* traw, int E) {
    int e = blockIdx.x * blockDim.x + threadIdx.x;
    if (e >= E) return;
    if (g_is64) {
        g_s[e] = (int)((const long long*)sraw)[e];
        g_t[e] = (int)((const long long*)traw)[e];
    } else {
        g_s[e] = ((const int*)sraw)[e];
        g_t[e] = ((const int*)traw)[e];
    }
}

// ---------------- producer row store: lane l owns channels [4l, 4l+4) ----------------
__device__ __forceinline__ void prod_store_row(char* Phi, char* Plo, int row, int lane,
                                               float p0, float p1, float p2, float p3) {
    uint32_t h0, l0, h1, l1;
    split2(p0, p1, h0, l0);
    split2(p2, p3, h1, l1);
    uint32_t off = swz(row, lane >> 1) + (lane & 1) * 8;
    uint2 h; h.x = h0; h.y = h1;
    uint2 l; l.x = l0; l.y = l1;
    *(uint2*)(Phi + off) = h;
    *(uint2*)(Plo + off) = l;
}

// ---------------- consumer GEMM core (8 warps, 64x32 warp tile) ----------------
__device__ __forceinline__ void consumer_gemm(uint32_t sPhi, uint32_t sPlo,
                                              uint32_t sWhi, uint32_t sWlo,
                                              int wm, int wn, int lane,
                                              float acc[4][4][4]) {
#pragma unroll
    for (int mb = 0; mb < 4; ++mb)
#pragma unroll
        for (int nb = 0; nb < 4; ++nb)
#pragma unroll
            for (int q = 0; q < 4; ++q) acc[mb][nb][q] = 0.f;

    int br0 = wn * 32 + (lane & 7) + ((lane >> 4) << 3);
    int ar_base = wm * 64 + (lane & 15);
    int cb = (lane >> 3) & 1;
    int ca = lane >> 4;

#pragma unroll
    for (int ks = 0; ks < 8; ++ks) {
        // hoist ALL fragment loads of this k-step ahead of the MMAs
        uint32_t Bh0[4], Bh1[4], Bl0[4], Bl1[4];
        uint32_t Ah[4][4], Al[4][4];
        {
            uint32_t offb0 = swz(br0, ks * 2 + cb);
            uint32_t offb1 = swz(br0 + 16, ks * 2 + cb);
            ldsm_x4(Bh0, sWhi + offb0);
            ldsm_x4(Bl0, sWlo + offb0);
            ldsm_x4(Bh1, sWhi + offb1);
            ldsm_x4(Bl1, sWlo + offb1);
        }
#pragma unroll
        for (int m = 0; m < 4; ++m) {
            uint32_t offa = swz(ar_base + m * 16, ks * 2 + ca);
            ldsm_x4(Ah[m], sPhi + offa);
            ldsm_x4(Al[m], sPlo + offa);
        }
#pragma unroll
        for (int mb = 0; mb < 4; ++mb) {
            mma_bf16(acc[mb][0], Ah[mb], Bh0);
            mma_bf16(acc[mb][0], Al[mb], Bh0);
            mma_bf16(acc[mb][0], Ah[mb], Bl0);
            mma_bf16(acc[mb][1], Ah[mb], Bh0 + 2);
            mma_bf16(acc[mb][1], Al[mb], Bh0 + 2);
            mma_bf16(acc[mb][1], Ah[mb], Bl0 + 2);
            mma_bf16(acc[mb][2], Ah[mb], Bh1);
            mma_bf16(acc[mb][2], Al[mb], Bh1);
            mma_bf16(acc[mb][2], Ah[mb], Bl1);
            mma_bf16(acc[mb][3], Ah[mb], Bh1 + 2);
            mma_bf16(acc[mb][3], Al[mb], Bh1 + 2);
            mma_bf16(acc[mb][3], Ah[mb], Bl1 + 2);
        }
    }
}

// ================= edge kernel =================
__global__ __launch_bounds__(WSTHREADS, 1)
void edge_ws_kernel(const float* __restrict__ ah, const float* __restrict__ bh,
                    const float* __restrict__ Wo, float* __restrict__ out,
                    int E, int nTiles) {
    extern __shared__ __align__(128) char sm[];
    char* Whi = sm;
    char* Wlo = sm + 32768;
    char* Pb  = sm + 65536;
    uint32_t ctrl = smem_u32(sm + 196608);  // full0, full1, empty0, empty1
    uint32_t sWhi = smem_u32(Whi), sWlo = smem_u32(Wlo);
    uint32_t sP = smem_u32(Pb);

    int tid = threadIdx.x;
    int wid = tid >> 5, lane = tid & 31;

    if (tid == 0) {
        mbar_init(ctrl + 0, 1);
        mbar_init(ctrl + 8, 1);
        mbar_init(ctrl + 16, 1);
        mbar_init(ctrl + 24, 1);
    }
    fill_W_split(Whi, Wlo, Wo, tid, WSTHREADS);
    __syncthreads();

    if (wid >= 8) {
        // ============ producer: prefetched indices + 4-row gather batches ============
        int pw = wid - 8;           // 0..7
        uint32_t pe[2] = {0, 0};
        int it = 0;
        for (int tile = blockIdx.x; tile < nTiles; tile += gridDim.x, ++it) {
            int b = it & 1;
            if (it >= 2) { mbar_wait(ctrl + 16 + b * 8, pe[b]); pe[b] ^= 1; }
            char* Phi = Pb + b * 65536;
            char* Plo = Phi + 32768;
            int base = tile * TILE;

            // prefetch all 16 row indices of this warp in one coalesced load
            int rsel = lane & 15;
            int esel = base + pw + 8 * rsel;
            if (esel >= E) esel = E - 1;
            int idxv = (lane < 16) ? g_s[esel] : g_t[esel];

#pragma unroll
            for (int ib = 0; ib < 4; ++ib) {
                float4 av[4], bv[4], kv[4], vv[4], rv[4];
#pragma unroll
                for (int j = 0; j < 4; ++j) {
                    int i = ib * 4 + j;
                    int e = base + pw + 8 * i;
                    int ec = (e < E) ? e : (E - 1);
                    int si = __shfl_sync(0xffffffffu, idxv, i);
                    int vi = __shfl_sync(0xffffffffu, idxv, 16 + i);
                    av[j] = __ldcs((const float4*)(ah) + (size_t)ec * 32 + lane);
                    bv[j] = __ldcs((const float4*)(bh) + (size_t)ec * 32 + lane);
                    kv[j] = *((const float4*)(g_K) + (size_t)si * 32 + lane);
                    vv[j] = *((const float4*)(g_V) + (size_t)vi * 32 + lane);
                    rv[j] = *((const float4*)(g_R) + (size_t)si * 32 + lane);
                }
#pragma unroll
                for (int j = 0; j < 4; ++j) {
                    int i = ib * 4 + j;
                    int row = pw + 8 * i;
                    float p0 = rv[j].x * __fdividef(av[j].x + kv[j].x * vv[j].x,
                                                    bv[j].x + kv[j].x + 1e-20f);
                    float p1 = rv[j].y * __fdividef(av[j].y + kv[j].y * vv[j].y,
                                                    bv[j].y + kv[j].y + 1e-20f);
                    float p2 = rv[j].z * __fdividef(av[j].z + kv[j].z * vv[j].z,
                                                    bv[j].z + kv[j].z + 1e-20f);
                    float p3 = rv[j].w * __fdividef(av[j].w + kv[j].w * vv[j].w,
                                                    bv[j].w + kv[j].w + 1e-20f);
                    prod_store_row(Phi, Plo, row, lane, p0, p1, p2, p3);
                }
            }
            BARSYNC(1);
            if (tid == 256) mbar_arrive(ctrl + b * 8);   // full[b]
        }
    } else {
        // ================= consumer =================
        int wm = wid >> 2, wn = wid & 3;
        uint32_t pf[2] = {0, 0};
        int it = 0;
        for (int tile = blockIdx.x; tile < nTiles; tile += gridDim.x, ++it) {
            int b = it & 1;
            mbar_wait(ctrl + b * 8, pf[b]); pf[b] ^= 1;
            uint32_t sPhi = sP + b * 65536;
            uint32_t sPlo = sPhi + 32768;

            float acc[4][4][4];
            consumer_gemm(sPhi, sPlo, sWhi, sWlo, wm, wn, lane, acc);

            BARSYNC(2);
            if (tid == 0) mbar_arrive(ctrl + 16 + b * 8);  // empty[b]

            int base = tile * TILE;
#pragma unroll
            for (int mb = 0; mb < 4; ++mb) {
                int rA = base + wm * 64 + mb * 16 + (lane >> 2);
                int rB = rA + 8;
#pragma unroll
                for (int nb = 0; nb < 4; ++nb) {
                    int col = wn * 32 + nb * 8 + (lane & 3) * 2;
                    if (rA < E) {
                        float2 v; v.x = acc[mb][nb][0]; v.y = acc[mb][nb][1];
                        __stcs((float2*)(out + (size_t)rA * CDIM + col), v);
                    }
                    if (rB < E) {
                        float2 v; v.x = acc[mb][nb][2]; v.y = acc[mb][nb][3];
                        __stcs((float2*)(out + (size_t)rB * CDIM + col), v);
                    }
                }
            }
        }
    }
}

// ================= node kernel =================
__global__ __launch_bounds__(WSTHREADS, 1)
void node_ws_kernel(const float* __restrict__ x, const float* __restrict__ prevx,
                    const float* __restrict__ Wk, const float* __restrict__ Wv,
                    const float* __restrict__ Wr,
                    const float* __restrict__ tmk, const float* __restrict__ tmv,
                    const float* __restrict__ tmr, int N, int nTiles) {
    extern __shared__ __align__(128) char sm[];
    char* Whi = sm;
    char* Wlo = sm + 32768;
    char* Pb  = sm + 65536;
    uint32_t ctrl = smem_u32(sm + 196608);
    uint32_t sWhi = smem_u32(Whi), sWlo = smem_u32(Wlo);
    uint32_t sP = smem_u32(Pb);

    int tid = threadIdx.x;
    int wid = tid >> 5, lane = tid & 31;
    int mat = blockIdx.y;
    const float* W  = (mat == 0) ? Wk  : (mat == 1) ? Wv  : Wr;
    const float* tm = (mat == 0) ? tmk : (mat == 1) ? tmv : tmr;
    float* dstG = (mat == 0) ? g_K : (mat == 1) ? g_V : g_R;

    if (tid == 0) {
        mbar_init(ctrl + 0, 1);
        mbar_init(ctrl + 8, 1);
        mbar_init(ctrl + 16, 1);
        mbar_init(ctrl + 24, 1);
    }
    fill_W_split(Whi, Wlo, W, tid, WSTHREADS);
    __syncthreads();

    if (wid >= 8) {
        int pw = wid - 8;
        float4 tv = *((const float4*)tm + lane);
        uint32_t pe[2] = {0, 0};
        int it = 0;
        for (int tile = blockIdx.x; tile < nTiles; tile += gridDim.x, ++it) {
            int b = it & 1;
            if (it >= 2) { mbar_wait(ctrl + 16 + b * 8, pe[b]); pe[b] ^= 1; }
            char* Phi = Pb + b * 65536;
            char* Plo = Phi + 32768;
            int base = tile * TILE;
#pragma unroll
            for (int ib = 0; ib < 4; ++ib) {
                float4 xv[4], pv[4];
#pragma unroll
                for (int j = 0; j < 4; ++j) {
                    int i = ib * 4 + j;
                    int node = base + pw + 8 * i;
                    int nc = (node < N) ? node : (N - 1);
                    xv[j] = *((const float4*)(x)     + (size_t)nc * 32 + lane);
                    pv[j] = *((const float4*)(prevx) + (size_t)nc * 32 + lane);
                }
#pragma unroll
                for (int j = 0; j < 4; ++j) {
                    int i = ib * 4 + j;
                    int row = pw + 8 * i;
                    float p0 = pv[j].x + tv.x * (xv[j].x - pv[j].x);
                    float p1 = pv[j].y + tv.y * (xv[j].y - pv[j].y);
                    float p2 = pv[j].z + tv.z * (xv[j].z - pv[j].z);
                    float p3 = pv[j].w + tv.w * (xv[j].w - pv[j].w);
                    prod_store_row(Phi, Plo, row, lane, p0, p1, p2, p3);
                }
            }
            BARSYNC(1);
            if (tid == 256) mbar_arrive(ctrl + b * 8);
        }
    } else {
        int wm = wid >> 2, wn = wid & 3;
        float wreg[4][2];
        if (mat == 1) {
#pragma unroll
            for (int nb = 0; nb < 4; ++nb) {
                int col = wn * 32 + nb * 8 + (lane & 3) * 2;
                wreg[nb][0] = g_w[col];
                wreg[nb][1] = g_w[col + 1];
            }
        }
        uint32_t pf[2] = {0, 0};
        int it = 0;
        for (int tile = blockIdx.x; tile < nTiles; tile += gridDim.x, ++it) {
            int b = it & 1;
            mbar_wait(ctrl + b * 8, pf[b]); pf[b] ^= 1;
            uint32_t sPhi = sP + b * 65536;
            uint32_t sPlo = sPhi + 32768;

            float acc[4][4][4];
            consumer_gemm(sPhi, sPlo, sWhi, sWlo, wm, wn, lane, acc);

            BARSYNC(2);
            if (tid == 0) mbar_arrive(ctrl + 16 + b * 8);

            int base = tile * TILE;
#pragma unroll
            for (int mb = 0; mb < 4; ++mb) {
                int rA = base + wm * 64 + mb * 16 + (lane >> 2);
#pragma unroll
                for (int nb = 0; nb < 4; ++nb) {
                    int col = wn * 32 + nb * 8 + (lane & 3) * 2;
#pragma unroll
                    for (int hh = 0; hh < 2; ++hh) {
                        int row = rA + hh * 8;
                        if (row >= N) continue;
                        float v0 = acc[mb][nb][hh * 2];
                        float v1 = acc[mb][nb][hh * 2 + 1];
                        float2 v;
                        if (mat == 0) {
                            v.x = __expf(fminf(v0, 60.0f));
                            v.y = __expf(fminf(v1, 60.0f));
                        } else if (mat == 1) {
                            v.x = v0 * wreg[nb][0];
                            v.y = v1 * wreg[nb][1];
                        } else {
                            v.x = __fdividef(1.0f, 1.0f + __expf(-v0));
                            v.y = __fdividef(1.0f, 1.0f + __expf(-v1));
                        }
                        *(float2*)(dstG + (size_t)row * CDIM + col) = v;
                    }
                }
            }
        }
    }
}

// ---------------- launch ----------------
extern "C" void kernel_launch(void* const* d_in, const int* in_sizes, int n_in,
                              void* d_out, int out_size) {
    const float* x      = (const float*)d_in[0];
    const float* prev_x = (const float*)d_in[1];
    const float* ah     = (const float*)d_in[2];
    const float* bh     = (const float*)d_in[3];
    const float* Wk     = (const float*)d_in[4];
    const float* Wv     = (const float*)d_in[5];
    const float* Wr     = (const float*)d_in[6];
    const float* Wo     = (const float*)d_in[7];
    const float* tmk    = (const float*)d_in[8];
    const float* tmv    = (const float*)d_in[9];
    const float* tmr    = (const float*)d_in[10];
    const float* tw     = (const float*)d_in[11];
    const void*  s      = d_in[12];
    const void*  t      = d_in[13];
    const void*  ip     = d_in[14];
    const void*  Tp     = d_in[15];

    int N = in_sizes[0] / CDIM;
    int E = in_sizes[2] / CDIM;

    cudaFuncSetAttribute(edge_ws_kernel, cudaFuncAttributeMaxDynamicSharedMemorySize, WS_SMEM);
    cudaFuncSetAttribute(node_ws_kernel, cudaFuncAttributeMaxDynamicSharedMemorySize, WS_SMEM);

    prep_kernel<<<1, 128>>>(tw, ip, Tp, s);
    idx_kernel<<<(E + 255) / 256, 256>>>(s, t, E);

    int nTilesN = (N + TILE - 1) / TILE;
    dim3 ngrid(49, 3);
    node_ws_kernel<<<ngrid, WSTHREADS, WS_SMEM>>>(x, prev_x, Wk, Wv, Wr,
                                                  tmk, tmv, tmr, N, nTilesN);

    int nTiles = (E + TILE - 1) / TILE;
    edge_ws_kernel<<<148, WSTHREADS, WS_SMEM>>>(ah, bh, Wo, (float*)d_out, E, nTiles);
}